// round 10
// baseline (speedup 1.0000x reference)
#include <cuda_runtime.h>
#include <cuda_bf16.h>
#include <cstdint>

// ---------------- problem constants ----------------
static constexpr int DIMD   = 256;     // embedding dim (GEMM K)
static constexpr int KCB    = 1024;    // codebook size (GEMM N)
static constexpr int NROW   = 32768;   // rows per input
static constexpr int ROWS   = 65536;   // both inputs
static constexpr int BM     = 64;      // rows per block
static constexpr int BN     = 128;     // cols per n-chunk
static constexpr int DC     = 64;      // d (k-dim) chunk
static constexpr int NCH    = KCB / BN;   // 8
static constexpr int DCH    = DIMD / DC;  // 4
static constexpr int THREADS = 256;
static constexpr int CAP    = 24;      // candidate list capacity per row
static constexpr float THR  = 0.01f;   // candidate threshold (>>12 sigma of bf16 noise)

static constexpr int XP = DIMD + 8;    // 264 bf16, X smem pitch
static constexpr int EP = DC + 8;      // 72 bf16,  E smem pitch
static constexpr int SP = BN + 4;      // 132 fp32, dist staging pitch (16B-aligned rows)

// ---------------- output layout (fp32 elements) ----------------
static constexpr size_t STE_SZ  = 8388608;            // 8*64*64*256
static constexpr size_t O_DIFF  = 4ull * STE_SZ;      // 33554432
static constexpr size_t O_IND   = O_DIFF + 4;         // 33554436
static constexpr size_t O_DIST  = O_IND + 4ull * NROW;// 33685508
static constexpr size_t DIST_SZ = (size_t)NROW * KCB; // 33554432

// ---------------- device scratch (no allocations allowed) ----------------
__device__ __align__(16) __nv_bfloat16 g_Eb[KCB * DIMD];    // [k][d] bf16
__device__ __align__(16) float         g_embT[KCB * DIMD];  // [k][d] fp32
__device__ float  g_cn[KCB];
__device__ double g_diff[2];

// ---------------- helpers ----------------
__device__ __forceinline__ void mma16816(float* c, const uint32_t* a, const uint32_t* b) {
    asm volatile(
        "mma.sync.aligned.m16n8k16.row.col.f32.bf16.bf16.f32 "
        "{%0,%1,%2,%3}, {%4,%5,%6,%7}, {%8,%9}, {%0,%1,%2,%3};\n"
        : "+f"(c[0]), "+f"(c[1]), "+f"(c[2]), "+f"(c[3])
        : "r"(a[0]), "r"(a[1]), "r"(a[2]), "r"(a[3]), "r"(b[0]), "r"(b[1]));
}

__device__ __forceinline__ void ldsm_x4(uint32_t addr, uint32_t* r) {
    asm volatile("ldmatrix.sync.aligned.m8n8.x4.shared.b16 {%0,%1,%2,%3}, [%4];"
                 : "=r"(r[0]), "=r"(r[1]), "=r"(r[2]), "=r"(r[3]) : "r"(addr));
}
__device__ __forceinline__ void ldsm_x2(uint32_t addr, uint32_t* r) {
    asm volatile("ldmatrix.sync.aligned.m8n8.x2.shared.b16 {%0,%1}, [%2];"
                 : "=r"(r[0]), "=r"(r[1]) : "r"(addr));
}

__device__ __forceinline__ void cpasync16(void* dst_smem, const void* src) {
    uint32_t d = (uint32_t)__cvta_generic_to_shared(dst_smem);
    asm volatile("cp.async.cg.shared.global [%0], [%1], 16;\n" :: "r"(d), "l"(src) : "memory");
}
__device__ __forceinline__ void cpasync_commit() {
    asm volatile("cp.async.commit_group;\n" ::: "memory");
}
template <int N>
__device__ __forceinline__ void cpasync_wait() {
    asm volatile("cp.async.wait_group %0;\n" :: "n"(N) : "memory");
}

__device__ __forceinline__ unsigned long long umin64(unsigned long long a, unsigned long long b) {
    return a < b ? a : b;
}

// Reference-numerics emulation (validated round 5):
// a = ascending-k fp32 FFMA chain; dist = fl(fl(rn - 2a) + cn)
__device__ __forceinline__ float emul_dist(const float* __restrict__ X, int col, float rn_em) {
    const float* e = g_embT + (size_t)col * DIMD;
    float a = 0.f;
    for (int d = 0; d < DIMD; d++)
        a = fmaf(X[d], e[d], a);
    return __fadd_rn(__fsub_rn(rn_em, 2.0f * a), g_cn[col]);
}

// rn emulation: lane-strided fp32 mul+add, shfl-down tree (full warp required)
__device__ __forceinline__ float emul_rn(const float* __restrict__ X, int lane) {
    float s = 0.f;
    #pragma unroll
    for (int j = 0; j < 8; j++) {
        float v = X[lane + 32 * j];
        s = __fadd_rn(s, __fmul_rn(v, v));
    }
    #pragma unroll
    for (int off = 16; off; off >>= 1)
        s = __fadd_rn(s, __shfl_down_sync(0xffffffffu, s, off));
    return __shfl_sync(0xffffffffu, s, 0);
}

// ---------------- K1: prep codebook (one warp per code) ----------------
__global__ void vq_prep_kernel(const float* __restrict__ embed) {
    const int warp = threadIdx.x >> 5, lane = threadIdx.x & 31;
    const int k = blockIdx.x * 8 + warp;      // grid 128 x 8 warps = 1024
    if (blockIdx.x == 0 && threadIdx.x == 0) { g_diff[0] = 0.0; g_diff[1] = 0.0; }
    double s = 0.0;
    #pragma unroll
    for (int j = 0; j < 8; j++) {
        int d = lane + 32 * j;
        float v = embed[d * KCB + k];
        g_embT[k * DIMD + d] = v;
        g_Eb[k * DIMD + d] = __float2bfloat16(v);
        s = fma((double)v, (double)v, s);
    }
    #pragma unroll
    for (int off = 16; off; off >>= 1)
        s += __shfl_down_sync(0xffffffffu, s, off);
    if (lane == 0) g_cn[k] = (float)s;
}

// ---------------- K2: fused dist + candidates + argmin + ste + diff ----------
// E double buffer (36864 B) is reused as the dist staging tile (64*132*4 = 33792 B)
// during each nc epilogue, after the mainloop for that nc has fully consumed it.
static constexpr size_t SMEM_BYTES =
    (size_t)BM * XP * 2            // X bf16                     33792
    + 2ull * BN * EP * 2           // E double buffer bf16       36864
    + (BN + 3 * BM) * 4            // cn, rn, minb, ccnt          1280
    + (size_t)BM * CAP * 8;        // candidate list             12288
// = 84224 bytes -> 2 CTAs/SM

__global__ __launch_bounds__(THREADS, 2)
void vq_main_kernel(const float* __restrict__ in_hr,
                    const float* __restrict__ in_lr,
                    float* __restrict__ out) {
    extern __shared__ char smem[];
    __nv_bfloat16* sX = (__nv_bfloat16*)smem;
    __nv_bfloat16* sE = sX + BM * XP;               // [2 buf][BN*EP]
    float* stage = (float*)sE;                      // epilogue reuse: [BM][SP]
    float* cn_s = (float*)((char*)sE + 2 * BN * EP * 2);
    float* rn_s = cn_s + BN;
    unsigned* minb = (unsigned*)(rn_s + BM);        // row min (float bits)
    int* ccnt = (int*)(minb + BM);
    unsigned long long* cand = (unsigned long long*)(ccnt + BM);   // [BM][CAP]

    const int tid  = threadIdx.x;
    const int bid  = blockIdx.x;
    const int input = bid >> 9;                 // 0: hr, 1: lr   (512 blocks each)
    const int lrb   = (bid & 511) * BM;         // local row base within input
    const float* X = (input == 0 ? in_hr : in_lr) + (size_t)lrb * DIMD;

    // ---- load X -> bf16 smem ----
    const float4* Xv = (const float4*)X;
    for (int i = tid; i < BM * DIMD / 4; i += THREADS) {
        float4 v = Xv[i];
        int row = i >> 6;
        int col = (i & 63) * 4;
        __nv_bfloat16* p = sX + row * XP + col;
        p[0] = __float2bfloat16(v.x);
        p[1] = __float2bfloat16(v.y);
        p[2] = __float2bfloat16(v.z);
        p[3] = __float2bfloat16(v.w);
    }
    if (tid < BM) { minb[tid] = 0xFFFFFFFFu; ccnt[tid] = 0; }

    // ---- row norms in fp64 (for the dist OUTPUT; tolerance loose) ----
    {
        int r  = tid >> 2;                 // 64 rows, 4 threads each
        int d0 = (tid & 3) * 64;
        const float* xp = X + r * DIMD + d0;
        double s = 0.0;
        #pragma unroll 4
        for (int d = 0; d < 64; d++) {
            double x = (double)xp[d];
            s = fma(x, x, s);
        }
        s += __shfl_down_sync(0xffffffffu, s, 2);
        s += __shfl_down_sync(0xffffffffu, s, 1);
        if ((tid & 3) == 0) rn_s[r] = (float)s;
    }
    __syncthreads();

    const int warp = tid >> 5, lane = tid & 31;
    const int wm = warp >> 2, wn = warp & 3;    // warp grid 2 (M) x 4 (N)
    const int g = lane >> 2, tg = lane & 3;
    const int rowA0 = wm * 32 + g;              // + mt*16 (+8)

    // ldmatrix lane->address offsets (in halves)
    int aRowOff[2], bRowOff[4];
    #pragma unroll
    for (int mt = 0; mt < 2; mt++)
        aRowOff[mt] = (wm * 32 + mt * 16 + (lane & 15)) * XP + (lane >> 4) * 8;
    #pragma unroll
    for (int nt = 0; nt < 4; nt++)
        bRowOff[nt] = (wn * 32 + nt * 8 + (lane & 7)) * EP + ((lane >> 3) & 1) * 8;

    const uint32_t sX_sa = (uint32_t)__cvta_generic_to_shared(sX);
    const uint32_t sE_sa = (uint32_t)__cvta_generic_to_shared(sE);

    float acc[2][4][4];
    float rm[4] = {3.4e38f, 3.4e38f, 3.4e38f, 3.4e38f};   // running min [mt][A/B]

    for (int nc = 0; nc < NCH; nc++) {
        __syncthreads();   // staging read-pass (prev nc) done before E prefetch
        if (tid < BN) cn_s[tid] = g_cn[nc * BN + tid];
        #pragma unroll
        for (int mt = 0; mt < 2; mt++)
            #pragma unroll
            for (int nt = 0; nt < 4; nt++)
                #pragma unroll
                for (int j = 0; j < 4; j++) acc[mt][nt][j] = 0.f;

        // prefetch dchunk 0: 128 rows x 64 bf16 (128B = 8 x 16B per row)
        {
            __nv_bfloat16* dst = sE;
            for (int i = tid; i < 1024; i += THREADS) {
                int row = i >> 3, seg = i & 7;
                size_t go = (size_t)(nc * BN + row) * DIMD + seg * 8;
                cpasync16(dst + row * EP + seg * 8, g_Eb + go);
            }
            cpasync_commit();
        }

        for (int dcx = 0; dcx < DCH; dcx++) {
            int cur = dcx & 1;
            if (dcx < DCH - 1) {
                __nv_bfloat16* dst = sE + (cur ^ 1) * BN * EP;
                int dcn = dcx + 1;
                for (int i = tid; i < 1024; i += THREADS) {
                    int row = i >> 3, seg = i & 7;
                    size_t go = (size_t)(nc * BN + row) * DIMD + dcn * DC + seg * 8;
                    cpasync16(dst + row * EP + seg * 8, g_Eb + go);
                }
                cpasync_commit();
                cpasync_wait<1>();
            } else {
                cpasync_wait<0>();
            }
            __syncthreads();

            const uint32_t Ec_sa = sE_sa + cur * BN * EP * 2;

            #pragma unroll
            for (int ks = 0; ks < 4; ks++) {
                uint32_t a[2][4], b[4][2];
                const int dA = dcx * DC + ks * 16;
                #pragma unroll
                for (int mt = 0; mt < 2; mt++)
                    ldsm_x4(sX_sa + (aRowOff[mt] + dA) * 2, a[mt]);
                #pragma unroll
                for (int nt = 0; nt < 4; nt++)
                    ldsm_x2(Ec_sa + (bRowOff[nt] + ks * 16) * 2, b[nt]);
                #pragma unroll
                for (int mt = 0; mt < 2; mt++)
                    #pragma unroll
                    for (int nt = 0; nt < 4; nt++)
                        mma16816(acc[mt][nt], a[mt], b[nt]);
            }
            __syncthreads();
        }
        __syncthreads();   // all warps done with E before staging overwrites it

        // ---- epilogue: dist -> stage, running min (value only), candidates ----
        {
            #pragma unroll
            for (int mt = 0; mt < 2; mt++) {
                const int rA = rowA0 + mt * 16;
                const int rB = rA + 8;
                const float rnA = rn_s[rA], rnB = rn_s[rB];
                #pragma unroll
                for (int nt = 0; nt < 4; nt++) {
                    const int c  = wn * 32 + nt * 8 + tg * 2;
                    const int gc = nc * BN + c;
                    const float cn0 = cn_s[c], cn1 = cn_s[c + 1];
                    const float* a = acc[mt][nt];
                    float v00 = fmaf(-2.0f, a[0], rnA) + cn0;
                    float v01 = fmaf(-2.0f, a[1], rnA) + cn1;
                    float v10 = fmaf(-2.0f, a[2], rnB) + cn0;
                    float v11 = fmaf(-2.0f, a[3], rnB) + cn1;
                    *(float2*)(stage + rA * SP + c) = make_float2(v00, v01);
                    *(float2*)(stage + rB * SP + c) = make_float2(v10, v11);
                    float mA = fminf(v00, v01);
                    float mB = fminf(v10, v11);
                    rm[mt * 2]     = fminf(rm[mt * 2], mA);
                    rm[mt * 2 + 1] = fminf(rm[mt * 2 + 1], mB);
                    if (mA <= rm[mt * 2] + THR) {   // rare
                        if (v00 <= rm[mt * 2] + THR) {
                            int p = atomicAdd(&ccnt[rA], 1);
                            if (p < CAP)
                                cand[rA * CAP + p] =
                                    ((unsigned long long)__float_as_uint(v00) << 32) | (unsigned)gc;
                        }
                        if (v01 <= rm[mt * 2] + THR) {
                            int p = atomicAdd(&ccnt[rA], 1);
                            if (p < CAP)
                                cand[rA * CAP + p] =
                                    ((unsigned long long)__float_as_uint(v01) << 32) | (unsigned)(gc + 1);
                        }
                    }
                    if (mB <= rm[mt * 2 + 1] + THR) {   // rare
                        if (v10 <= rm[mt * 2 + 1] + THR) {
                            int p = atomicAdd(&ccnt[rB], 1);
                            if (p < CAP)
                                cand[rB * CAP + p] =
                                    ((unsigned long long)__float_as_uint(v10) << 32) | (unsigned)gc;
                        }
                        if (v11 <= rm[mt * 2 + 1] + THR) {
                            int p = atomicAdd(&ccnt[rB], 1);
                            if (p < CAP)
                                cand[rB * CAP + p] =
                                    ((unsigned long long)__float_as_uint(v11) << 32) | (unsigned)(gc + 1);
                        }
                    }
                }
            }
        }
        __syncthreads();

        // ---- coalesced store pass: LDS.128 + STG.128, streaming, x2 slots ----
        {
            const size_t dbase = O_DIST + (size_t)input * DIST_SZ
                                 + (size_t)lrb * KCB + (size_t)nc * BN;
            #pragma unroll
            for (int rr = 0; rr < 8; rr++) {
                const int r = warp * 8 + rr;
                float4 v = *(const float4*)(stage + r * SP + lane * 4);
                float* p = out + dbase + (size_t)r * KCB + lane * 4;
                __stcs((float4*)p, v);
                __stcs((float4*)(p + 2ull * DIST_SZ), v);
            }
        }
        __syncthreads();           // stage reusable next nc (drain done)
    }

    // ---- merge per-thread running mins into per-row min ----
    #pragma unroll
    for (int i = 0; i < 4; i++) {
        float m = rm[i];
        m = fminf(m, __shfl_xor_sync(0xffffffffu, m, 1));
        m = fminf(m, __shfl_xor_sync(0xffffffffu, m, 2));
        if (tg == 0) {
            const int r = rowA0 + (i >> 1) * 16 + (i & 1) * 8;
            atomicMin(&minb[r], __float_as_uint(m));
        }
    }
    __syncthreads();

    // ---- final epilogue: tie resolution, indices, gather, ste, diff ----
    {
        double dsum = 0.0;
        const size_t steA = (size_t)input * STE_SZ;
        const size_t steB = steA + 2ull * STE_SZ;
        const size_t indA = O_IND + (size_t)input * NROW;
        const size_t indB = indA + 2ull * NROW;
        for (int rr = 0; rr < 8; rr++) {
            const int r = warp * 8 + rr;
            const float fminv = __uint_as_float(minb[r]);
            const int cnt = ccnt[r];
            const float* Xr = X + (size_t)r * DIMD;

            unsigned win;
            if (cnt <= CAP) {
                unsigned long long ck = (lane < cnt) ? cand[r * CAP + lane] : ~0ull;
                float cv = __uint_as_float((unsigned)(ck >> 32));
                bool qual = (lane < cnt) && (cv <= fminv + THR);
                unsigned bal = __ballot_sync(0xffffffffu, qual);
                if (__popc(bal) == 1) {
                    int src = __ffs(bal) - 1;
                    win = __shfl_sync(0xffffffffu, (unsigned)(ck & 0xffffffffull), src);
                } else {
                    const float rn_em = emul_rn(Xr, lane);
                    unsigned long long key = ~0ull;
                    if (qual) {
                        const int cc = (int)(ck & 0xffffffffull);
                        float dd = emul_dist(Xr, cc, rn_em);
                        key = ((unsigned long long)__float_as_uint(dd) << 32) | (unsigned)cc;
                    }
                    #pragma unroll
                    for (int off = 16; off; off >>= 1)
                        key = umin64(key, __shfl_xor_sync(0xffffffffu, key, off));
                    win = (unsigned)(key & 0xffffffffull);
                }
            } else {
                // overflow fallback: rescan the written dist row (L2-hot)
                const float rn_em = emul_rn(Xr, lane);
                const float* drow = out + O_DIST + (size_t)input * DIST_SZ
                                    + (size_t)(lrb + r) * KCB;
                unsigned long long key = ~0ull;
                for (int j = 0; j < 32; j++) {
                    int c = lane + 32 * j;
                    float v = drow[c];
                    if (v <= fminv + THR) {
                        float dd = emul_dist(Xr, c, rn_em);
                        key = umin64(key,
                            ((unsigned long long)__float_as_uint(dd) << 32) | (unsigned)c);
                    }
                }
                #pragma unroll
                for (int off = 16; off; off >>= 1)
                    key = umin64(key, __shfl_xor_sync(0xffffffffu, key, off));
                win = (unsigned)(key & 0xffffffffull);
            }

            const size_t grow = (size_t)(lrb + r);
            if (lane == 0) {
                float fi = (float)win;
                out[indA + grow] = fi;
                out[indB + grow] = fi;
            }
            const float4* qp = (const float4*)(g_embT + (size_t)win * DIMD) + lane * 2;
            const float4 q0 = qp[0], q1 = qp[1];
            const float4* xg = (const float4*)Xr + lane * 2;
            const float4 x0 = xg[0], x1 = xg[1];
            float xr[8] = {x0.x, x0.y, x0.z, x0.w, x1.x, x1.y, x1.z, x1.w};
            float qv[8] = {q0.x, q0.y, q0.z, q0.w, q1.x, q1.y, q1.z, q1.w};
            float sv[8];
            float fs = 0.f;
            #pragma unroll
            for (int j = 0; j < 8; j++) {
                float dv = __fsub_rn(qv[j], xr[j]);
                sv[j] = __fadd_rn(xr[j], dv);     // exact STE forward as in reference
                fs = fmaf(dv, dv, fs);
            }
            dsum += (double)fs;
            const size_t o = grow * DIMD + lane * 8;
            __stcs((float4*)(out + steA + o),     make_float4(sv[0], sv[1], sv[2], sv[3]));
            __stcs((float4*)(out + steA + o + 4), make_float4(sv[4], sv[5], sv[6], sv[7]));
            __stcs((float4*)(out + steB + o),     make_float4(sv[0], sv[1], sv[2], sv[3]));
            __stcs((float4*)(out + steB + o + 4), make_float4(sv[4], sv[5], sv[6], sv[7]));
        }
        #pragma unroll
        for (int off = 16; off > 0; off >>= 1)
            dsum += __shfl_down_sync(0xffffffffu, dsum, off);
        if (lane == 0) atomicAdd(&g_diff[input], dsum);
    }
}

// ---------------- K3: finalize diffs ----------------
__global__ void vq_fin_kernel(float* __restrict__ out) {
    if (threadIdx.x == 0) {
        float dh = (float)(g_diff[0] / (double)STE_SZ);
        float dl = (float)(g_diff[1] / (double)STE_SZ);
        out[O_DIFF + 0] = dh;
        out[O_DIFF + 1] = dl;
        out[O_DIFF + 2] = dh;
        out[O_DIFF + 3] = dl;
    }
}

// ---------------- launch ----------------
extern "C" void kernel_launch(void* const* d_in, const int* in_sizes, int n_in,
                              void* d_out, int out_size) {
    const float* in_hr = (const float*)d_in[0];
    const float* in_lr = (const float*)d_in[1];
    const float* embed = (const float*)d_in[2];
    float* out = (float*)d_out;
    (void)in_sizes; (void)n_in; (void)out_size;

    cudaFuncSetAttribute(vq_main_kernel,
                         cudaFuncAttributeMaxDynamicSharedMemorySize,
                         (int)SMEM_BYTES);

    vq_prep_kernel<<<128, 256>>>(embed);
    vq_main_kernel<<<ROWS / BM, THREADS, SMEM_BYTES>>>(in_hr, in_lr, out);
    vq_fin_kernel<<<1, 32>>>(out);
}

// round 11
// speedup vs baseline: 2.1765x; 2.1765x over previous
#include <cuda_runtime.h>
#include <cuda_bf16.h>
#include <cstdint>

// ---------------- problem constants ----------------
static constexpr int DIMD   = 256;     // embedding dim (GEMM K)
static constexpr int KCB    = 1024;    // codebook size (GEMM N)
static constexpr int NROW   = 32768;   // rows per input
static constexpr int ROWS   = 65536;   // both inputs
static constexpr int BM     = 64;      // rows per block
static constexpr int BN     = 128;     // cols per n-chunk
static constexpr int DC     = 64;      // d (k-dim) chunk
static constexpr int NCH    = KCB / BN;   // 8
static constexpr int DCH    = DIMD / DC;  // 4
static constexpr int THREADS = 256;
static constexpr int CAP    = 24;      // candidate list capacity per row
static constexpr float THR  = 0.01f;   // candidate threshold (>>12 sigma of bf16 noise)

static constexpr int XP = DIMD + 8;    // 264 bf16, X smem pitch
static constexpr int EP = DC + 8;      // 72 bf16,  E smem pitch
static constexpr int SP = BN + 4;      // 132 fp32, dist staging pitch (16B-aligned rows)

// ---------------- output layout (fp32 elements) ----------------
static constexpr size_t STE_SZ  = 8388608;            // 8*64*64*256
static constexpr size_t O_DIFF  = 4ull * STE_SZ;      // 33554432
static constexpr size_t O_IND   = O_DIFF + 4;         // 33554436
static constexpr size_t O_DIST  = O_IND + 4ull * NROW;// 33685508
static constexpr size_t DIST_SZ = (size_t)NROW * KCB; // 33554432

// ---------------- device scratch (no allocations allowed) ----------------
__device__ __align__(16) __nv_bfloat16 g_Eb[KCB * DIMD];    // [k][d] bf16
__device__ __align__(16) float         g_embT[KCB * DIMD];  // [k][d] fp32
__device__ float  g_cn[KCB];
__device__ double g_diff[2];

// ---------------- helpers ----------------
__device__ __forceinline__ void mma16816(float* c, const uint32_t* a, const uint32_t* b) {
    asm volatile(
        "mma.sync.aligned.m16n8k16.row.col.f32.bf16.bf16.f32 "
        "{%0,%1,%2,%3}, {%4,%5,%6,%7}, {%8,%9}, {%0,%1,%2,%3};\n"
        : "+f"(c[0]), "+f"(c[1]), "+f"(c[2]), "+f"(c[3])
        : "r"(a[0]), "r"(a[1]), "r"(a[2]), "r"(a[3]), "r"(b[0]), "r"(b[1]));
}

__device__ __forceinline__ void ldsm_x4(uint32_t addr, uint32_t* r) {
    asm volatile("ldmatrix.sync.aligned.m8n8.x4.shared.b16 {%0,%1,%2,%3}, [%4];"
                 : "=r"(r[0]), "=r"(r[1]), "=r"(r[2]), "=r"(r[3]) : "r"(addr));
}
__device__ __forceinline__ void ldsm_x2(uint32_t addr, uint32_t* r) {
    asm volatile("ldmatrix.sync.aligned.m8n8.x2.shared.b16 {%0,%1}, [%2];"
                 : "=r"(r[0]), "=r"(r[1]) : "r"(addr));
}

__device__ __forceinline__ void cpasync16(void* dst_smem, const void* src) {
    uint32_t d = (uint32_t)__cvta_generic_to_shared(dst_smem);
    asm volatile("cp.async.cg.shared.global [%0], [%1], 16;\n" :: "r"(d), "l"(src) : "memory");
}
__device__ __forceinline__ void cpasync_commit() {
    asm volatile("cp.async.commit_group;\n" ::: "memory");
}
template <int N>
__device__ __forceinline__ void cpasync_wait() {
    asm volatile("cp.async.wait_group %0;\n" :: "n"(N) : "memory");
}

__device__ __forceinline__ unsigned long long umin64(unsigned long long a, unsigned long long b) {
    return a < b ? a : b;
}

// Reference-numerics emulation (validated round 5):
// a = ascending-k fp32 FFMA chain; dist = fl(fl(rn - 2a) + cn)
__device__ __forceinline__ float emul_dist(const float* __restrict__ X, int col, float rn_em) {
    const float* e = g_embT + (size_t)col * DIMD;
    float a = 0.f;
    for (int d = 0; d < DIMD; d++)
        a = fmaf(X[d], e[d], a);
    return __fadd_rn(__fsub_rn(rn_em, 2.0f * a), g_cn[col]);
}

// rn emulation: lane-strided fp32 mul+add, shfl-down tree (full warp required)
__device__ __forceinline__ float emul_rn(const float* __restrict__ X, int lane) {
    float s = 0.f;
    #pragma unroll
    for (int j = 0; j < 8; j++) {
        float v = X[lane + 32 * j];
        s = __fadd_rn(s, __fmul_rn(v, v));
    }
    #pragma unroll
    for (int off = 16; off; off >>= 1)
        s = __fadd_rn(s, __shfl_down_sync(0xffffffffu, s, off));
    return __shfl_sync(0xffffffffu, s, 0);
}

// ---------------- K1: prep codebook (one warp per code) ----------------
__global__ void vq_prep_kernel(const float* __restrict__ embed) {
    const int warp = threadIdx.x >> 5, lane = threadIdx.x & 31;
    const int k = blockIdx.x * 8 + warp;      // grid 128 x 8 warps = 1024
    if (blockIdx.x == 0 && threadIdx.x == 0) { g_diff[0] = 0.0; g_diff[1] = 0.0; }
    double s = 0.0;
    #pragma unroll
    for (int j = 0; j < 8; j++) {
        int d = lane + 32 * j;
        float v = embed[d * KCB + k];
        g_embT[k * DIMD + d] = v;
        g_Eb[k * DIMD + d] = __float2bfloat16(v);
        s = fma((double)v, (double)v, s);
    }
    #pragma unroll
    for (int off = 16; off; off >>= 1)
        s += __shfl_down_sync(0xffffffffu, s, off);
    if (lane == 0) g_cn[k] = (float)s;
}

// ---------------- K2: fused dist + candidates + argmin + ste + diff ----------
// E double buffer (36864 B) is reused as the dist staging tile (64*132*4 = 33792 B)
// during each nc epilogue, after the mainloop for that nc has fully consumed it.
static constexpr size_t SMEM_BYTES =
    (size_t)BM * XP * 2            // X bf16                     33792
    + 2ull * BN * EP * 2           // E double buffer bf16       36864
    + (BN + BM) * 4                // cn, rn                       768
    + BM * 8                       // minkey                       512
    + (size_t)BM * CAP * 8         // candidate list             12288
    + BM * 4;                      // candidate counts             256
// = 84480 bytes -> 2 CTAs/SM

__global__ __launch_bounds__(THREADS, 2)
void vq_main_kernel(const float* __restrict__ in_hr,
                    const float* __restrict__ in_lr,
                    float* __restrict__ out) {
    extern __shared__ char smem[];
    __nv_bfloat16* sX = (__nv_bfloat16*)smem;
    __nv_bfloat16* sE = sX + BM * XP;               // [2 buf][BN*EP]
    float* stage = (float*)sE;                      // epilogue reuse: [BM][SP]
    float* cn_s = (float*)((char*)sE + 2 * BN * EP * 2);
    float* rn_s = cn_s + BN;
    unsigned long long* minkey = (unsigned long long*)(rn_s + BM);
    unsigned long long* cand   = minkey + BM;       // [BM][CAP]
    int* ccnt = (int*)(cand + BM * CAP);

    const int tid  = threadIdx.x;
    const int bid  = blockIdx.x;
    const int input = bid >> 9;                 // 0: hr, 1: lr   (512 blocks each)
    const int lrb   = (bid & 511) * BM;         // local row base within input
    const float* X = (input == 0 ? in_hr : in_lr) + (size_t)lrb * DIMD;

    // ---- load X -> bf16 smem ----
    const float4* Xv = (const float4*)X;
    for (int i = tid; i < BM * DIMD / 4; i += THREADS) {
        float4 v = Xv[i];
        int row = i >> 6;
        int col = (i & 63) * 4;
        __nv_bfloat16* p = sX + row * XP + col;
        p[0] = __float2bfloat16(v.x);
        p[1] = __float2bfloat16(v.y);
        p[2] = __float2bfloat16(v.z);
        p[3] = __float2bfloat16(v.w);
    }
    if (tid < BM) { minkey[tid] = ~0ull; ccnt[tid] = 0; }

    // ---- row norms in fp64 (for the dist OUTPUT; tolerance loose) ----
    {
        int r  = tid >> 2;                 // 64 rows, 4 threads each
        int d0 = (tid & 3) * 64;
        const float* xp = X + r * DIMD + d0;
        double s = 0.0;
        #pragma unroll 4
        for (int d = 0; d < 64; d++) {
            double x = (double)xp[d];
            s = fma(x, x, s);
        }
        s += __shfl_down_sync(0xffffffffu, s, 2);
        s += __shfl_down_sync(0xffffffffu, s, 1);
        if ((tid & 3) == 0) rn_s[r] = (float)s;
    }
    __syncthreads();

    const int warp = tid >> 5, lane = tid & 31;
    const int wm = warp >> 2, wn = warp & 3;    // warp grid 2 (M) x 4 (N)
    const int g = lane >> 2, tg = lane & 3;
    const int rowA0 = wm * 32 + g;              // + mt*16 (+8)

    // ldmatrix lane->address offsets (in halves)
    int aRowOff[2], bRowOff[4];
    #pragma unroll
    for (int mt = 0; mt < 2; mt++)
        aRowOff[mt] = (wm * 32 + mt * 16 + (lane & 15)) * XP + (lane >> 4) * 8;
    #pragma unroll
    for (int nt = 0; nt < 4; nt++)
        bRowOff[nt] = (wn * 32 + nt * 8 + (lane & 7)) * EP + ((lane >> 3) & 1) * 8;

    const uint32_t sX_sa = (uint32_t)__cvta_generic_to_shared(sX);
    const uint32_t sE_sa = (uint32_t)__cvta_generic_to_shared(sE);

    float acc[2][4][4];

    for (int nc = 0; nc < NCH; nc++) {
        __syncthreads();   // staging read-pass (prev nc) done before E prefetch
        if (tid < BN) cn_s[tid] = g_cn[nc * BN + tid];
        #pragma unroll
        for (int mt = 0; mt < 2; mt++)
            #pragma unroll
            for (int nt = 0; nt < 4; nt++)
                #pragma unroll
                for (int j = 0; j < 4; j++) acc[mt][nt][j] = 0.f;

        // prefetch dchunk 0: 128 rows x 64 bf16 (128B = 8 x 16B per row)
        {
            __nv_bfloat16* dst = sE;
            for (int i = tid; i < 1024; i += THREADS) {
                int row = i >> 3, seg = i & 7;
                size_t go = (size_t)(nc * BN + row) * DIMD + seg * 8;
                cpasync16(dst + row * EP + seg * 8, g_Eb + go);
            }
            cpasync_commit();
        }

        for (int dcx = 0; dcx < DCH; dcx++) {
            int cur = dcx & 1;
            if (dcx < DCH - 1) {
                __nv_bfloat16* dst = sE + (cur ^ 1) * BN * EP;
                int dcn = dcx + 1;
                for (int i = tid; i < 1024; i += THREADS) {
                    int row = i >> 3, seg = i & 7;
                    size_t go = (size_t)(nc * BN + row) * DIMD + dcn * DC + seg * 8;
                    cpasync16(dst + row * EP + seg * 8, g_Eb + go);
                }
                cpasync_commit();
                cpasync_wait<1>();
            } else {
                cpasync_wait<0>();
            }
            __syncthreads();

            const uint32_t Ec_sa = sE_sa + cur * BN * EP * 2;

            #pragma unroll
            for (int ks = 0; ks < 4; ks++) {
                uint32_t a[2][4], b[4][2];
                const int dA = dcx * DC + ks * 16;
                #pragma unroll
                for (int mt = 0; mt < 2; mt++)
                    ldsm_x4(sX_sa + (aRowOff[mt] + dA) * 2, a[mt]);
                #pragma unroll
                for (int nt = 0; nt < 4; nt++)
                    ldsm_x2(Ec_sa + (bRowOff[nt] + ks * 16) * 2, b[nt]);
                #pragma unroll
                for (int mt = 0; mt < 2; mt++)
                    #pragma unroll
                    for (int nt = 0; nt < 4; nt++)
                        mma16816(acc[mt][nt], a[mt], b[nt]);
            }
            __syncthreads();   // last dcx: doubles as the pre-staging barrier
        }

        // ---- epilogue: stage dist in smem, running argmin, candidates ----
        {
            #pragma unroll
            for (int mt = 0; mt < 2; mt++) {
                const int rA = rowA0 + mt * 16;
                const int rB = rA + 8;
                const float rnA = rn_s[rA], rnB = rn_s[rB];
                float vA[8], vB[8];
                unsigned long long kA = ~0ull, kB = ~0ull;
                #pragma unroll
                for (int nt = 0; nt < 4; nt++) {
                    const int c  = wn * 32 + nt * 8 + tg * 2;
                    const int gc = nc * BN + c;
                    const float cn0 = cn_s[c], cn1 = cn_s[c + 1];
                    const float* a = acc[mt][nt];
                    float v00 = fmaf(-2.0f, a[0], rnA) + cn0;
                    float v01 = fmaf(-2.0f, a[1], rnA) + cn1;
                    float v10 = fmaf(-2.0f, a[2], rnB) + cn0;
                    float v11 = fmaf(-2.0f, a[3], rnB) + cn1;
                    vA[nt * 2] = v00; vA[nt * 2 + 1] = v01;
                    vB[nt * 2] = v10; vB[nt * 2 + 1] = v11;
                    *(float2*)(stage + rA * SP + c) = make_float2(v00, v01);
                    *(float2*)(stage + rB * SP + c) = make_float2(v10, v11);
                    unsigned long long k00 = ((unsigned long long)__float_as_uint(v00) << 32) | (unsigned)gc;
                    unsigned long long k01 = ((unsigned long long)__float_as_uint(v01) << 32) | (unsigned)(gc + 1);
                    unsigned long long k10 = ((unsigned long long)__float_as_uint(v10) << 32) | (unsigned)gc;
                    unsigned long long k11 = ((unsigned long long)__float_as_uint(v11) << 32) | (unsigned)(gc + 1);
                    kA = umin64(kA, umin64(k00, k01));
                    kB = umin64(kB, umin64(k10, k11));
                }
                kA = umin64(kA, __shfl_xor_sync(0xffffffffu, kA, 1));
                kA = umin64(kA, __shfl_xor_sync(0xffffffffu, kA, 2));
                kB = umin64(kB, __shfl_xor_sync(0xffffffffu, kB, 1));
                kB = umin64(kB, __shfl_xor_sync(0xffffffffu, kB, 2));

                // reference levels for collection (>= final min -> superset)
                const float refA = __uint_as_float((unsigned)(umin64(minkey[rA], kA) >> 32)) + THR;
                const float refB = __uint_as_float((unsigned)(umin64(minkey[rB], kB) >> 32)) + THR;
                #pragma unroll
                for (int nt = 0; nt < 4; nt++) {
                    const int gc = nc * BN + wn * 32 + nt * 8 + tg * 2;
                    #pragma unroll
                    for (int q = 0; q < 2; q++) {
                        if (vA[nt * 2 + q] <= refA) {
                            int p = atomicAdd(&ccnt[rA], 1);
                            if (p < CAP)
                                cand[rA * CAP + p] =
                                    ((unsigned long long)__float_as_uint(vA[nt * 2 + q]) << 32) | (unsigned)(gc + q);
                        }
                        if (vB[nt * 2 + q] <= refB) {
                            int p = atomicAdd(&ccnt[rB], 1);
                            if (p < CAP)
                                cand[rB * CAP + p] =
                                    ((unsigned long long)__float_as_uint(vB[nt * 2 + q]) << 32) | (unsigned)(gc + q);
                        }
                    }
                }
                if (tg == 0) {
                    atomicMin(&minkey[rA], kA);
                    atomicMin(&minkey[rB], kB);
                }
            }
        }
        __syncthreads();

        // ---- coalesced store pass: 512B per STG.128 instruction, streaming ----
        {
            const size_t dbase = O_DIST + (size_t)input * DIST_SZ
                                 + (size_t)lrb * KCB + (size_t)nc * BN;
            #pragma unroll
            for (int rr = 0; rr < 8; rr++) {
                const int r = warp * 8 + rr;
                float4 v = *(const float4*)(stage + r * SP + lane * 4);
                float* p = out + dbase + (size_t)r * KCB + lane * 4;
                __stcs((float4*)p, v);
                __stcs((float4*)(p + 2ull * DIST_SZ), v);
            }
        }
    }
    __syncthreads();

    // ---- final epilogue: tie resolution, indices, gather, ste, diff ----
    {
        double dsum = 0.0;
        const size_t steA = (size_t)input * STE_SZ;
        const size_t steB = steA + 2ull * STE_SZ;
        const size_t indA = O_IND + (size_t)input * NROW;
        const size_t indB = indA + 2ull * NROW;
        for (int rr = 0; rr < 8; rr++) {
            const int r = warp * 8 + rr;
            const unsigned long long fkey = minkey[r];
            const float fminv = __uint_as_float((unsigned)(fkey >> 32));
            const int cnt = ccnt[r];
            const float* Xr = X + (size_t)r * DIMD;

            unsigned win;
            if (cnt <= CAP) {
                unsigned long long ck = (lane < cnt) ? cand[r * CAP + lane] : ~0ull;
                float cv = __uint_as_float((unsigned)(ck >> 32));
                bool qual = (lane < cnt) && (cv <= fminv + THR);
                unsigned bal = __ballot_sync(0xffffffffu, qual);
                if (__popc(bal) == 1) {
                    win = (unsigned)(fkey & 0xffffffffull);
                } else {
                    const float rn_em = emul_rn(Xr, lane);
                    unsigned long long key = ~0ull;
                    if (qual) {
                        const int cc = (int)(ck & 0xffffffffull);
                        float dd = emul_dist(Xr, cc, rn_em);
                        key = ((unsigned long long)__float_as_uint(dd) << 32) | (unsigned)cc;
                    }
                    #pragma unroll
                    for (int off = 16; off; off >>= 1)
                        key = umin64(key, __shfl_xor_sync(0xffffffffu, key, off));
                    win = (unsigned)(key & 0xffffffffull);
                }
            } else {
                // overflow fallback: rescan the written dist row (L2-hot)
                const float rn_em = emul_rn(Xr, lane);
                const float* drow = out + O_DIST + (size_t)input * DIST_SZ
                                    + (size_t)(lrb + r) * KCB;
                unsigned long long key = ~0ull;
                for (int j = 0; j < 32; j++) {
                    int c = lane + 32 * j;
                    float v = drow[c];
                    if (v <= fminv + THR) {
                        float dd = emul_dist(Xr, c, rn_em);
                        key = umin64(key,
                            ((unsigned long long)__float_as_uint(dd) << 32) | (unsigned)c);
                    }
                }
                #pragma unroll
                for (int off = 16; off; off >>= 1)
                    key = umin64(key, __shfl_xor_sync(0xffffffffu, key, off));
                win = (unsigned)(key & 0xffffffffull);
            }

            const size_t grow = (size_t)(lrb + r);
            if (lane == 0) {
                float fi = (float)win;
                out[indA + grow] = fi;
                out[indB + grow] = fi;
            }
            const float4* qp = (const float4*)(g_embT + (size_t)win * DIMD) + lane * 2;
            const float4 q0 = qp[0], q1 = qp[1];
            const float4* xg = (const float4*)Xr + lane * 2;
            const float4 x0 = xg[0], x1 = xg[1];
            float xr[8] = {x0.x, x0.y, x0.z, x0.w, x1.x, x1.y, x1.z, x1.w};
            float qv[8] = {q0.x, q0.y, q0.z, q0.w, q1.x, q1.y, q1.z, q1.w};
            float sv[8];
            float fs = 0.f;
            #pragma unroll
            for (int j = 0; j < 8; j++) {
                float dv = __fsub_rn(qv[j], xr[j]);
                sv[j] = __fadd_rn(xr[j], dv);     // exact STE forward as in reference
                fs = fmaf(dv, dv, fs);
            }
            dsum += (double)fs;
            const size_t o = grow * DIMD + lane * 8;
            __stcs((float4*)(out + steA + o),     make_float4(sv[0], sv[1], sv[2], sv[3]));
            __stcs((float4*)(out + steA + o + 4), make_float4(sv[4], sv[5], sv[6], sv[7]));
            __stcs((float4*)(out + steB + o),     make_float4(sv[0], sv[1], sv[2], sv[3]));
            __stcs((float4*)(out + steB + o + 4), make_float4(sv[4], sv[5], sv[6], sv[7]));
        }
        #pragma unroll
        for (int off = 16; off > 0; off >>= 1)
            dsum += __shfl_down_sync(0xffffffffu, dsum, off);
        if (lane == 0) atomicAdd(&g_diff[input], dsum);
    }
}

// ---------------- K3: finalize diffs ----------------
__global__ void vq_fin_kernel(float* __restrict__ out) {
    if (threadIdx.x == 0) {
        float dh = (float)(g_diff[0] / (double)STE_SZ);
        float dl = (float)(g_diff[1] / (double)STE_SZ);
        out[O_DIFF + 0] = dh;
        out[O_DIFF + 1] = dl;
        out[O_DIFF + 2] = dh;
        out[O_DIFF + 3] = dl;
    }
}

// ---------------- launch ----------------
extern "C" void kernel_launch(void* const* d_in, const int* in_sizes, int n_in,
                              void* d_out, int out_size) {
    const float* in_hr = (const float*)d_in[0];
    const float* in_lr = (const float*)d_in[1];
    const float* embed = (const float*)d_in[2];
    float* out = (float*)d_out;
    (void)in_sizes; (void)n_in; (void)out_size;

    cudaFuncSetAttribute(vq_main_kernel,
                         cudaFuncAttributeMaxDynamicSharedMemorySize,
                         (int)SMEM_BYTES);

    vq_prep_kernel<<<128, 256>>>(embed);
    vq_main_kernel<<<ROWS / BM, THREADS, SMEM_BYTES>>>(in_hr, in_lr, out);
    vq_fin_kernel<<<1, 32>>>(out);
}

// round 12
// speedup vs baseline: 2.1799x; 1.0015x over previous
#include <cuda_runtime.h>
#include <cuda_bf16.h>
#include <cstdint>

// ---------------- problem constants ----------------
static constexpr int DIMD   = 256;     // embedding dim (GEMM K)
static constexpr int KCB    = 1024;    // codebook size (GEMM N)
static constexpr int NROW   = 32768;   // rows per input
static constexpr int ROWS   = 65536;   // both inputs
static constexpr int BM     = 64;      // rows per block
static constexpr int BN     = 128;     // cols per n-chunk
static constexpr int DC     = 64;      // d (k-dim) chunk
static constexpr int NCH    = KCB / BN;   // 8
static constexpr int DCH    = DIMD / DC;  // 4
static constexpr int THREADS = 256;
static constexpr int CAP    = 24;      // candidate list capacity per row
static constexpr float THR  = 0.01f;   // candidate threshold (>>12 sigma of bf16 noise)

static constexpr int XP = DIMD + 8;    // 264 bf16, X smem pitch
static constexpr int EP = DC + 8;      // 72 bf16,  E smem pitch
static constexpr int SP = BN + 4;      // 132 fp32, dist staging pitch (16B-aligned rows)

// ---------------- output layout (fp32 elements) ----------------
static constexpr size_t STE_SZ  = 8388608;            // 8*64*64*256
static constexpr size_t O_DIFF  = 4ull * STE_SZ;      // 33554432
static constexpr size_t O_IND   = O_DIFF + 4;         // 33554436
static constexpr size_t O_DIST  = O_IND + 4ull * NROW;// 33685508
static constexpr size_t DIST_SZ = (size_t)NROW * KCB; // 33554432

// ---------------- device scratch (no allocations allowed) ----------------
__device__ __align__(16) __nv_bfloat16 g_Eb[KCB * DIMD];    // [k][d] bf16
__device__ __align__(16) float         g_embT[KCB * DIMD];  // [k][d] fp32
__device__ float  g_cn[KCB];
__device__ double g_diff[2];
__device__ unsigned g_done;            // completion counter for in-kernel finalize

// ---------------- helpers ----------------
__device__ __forceinline__ void mma16816(float* c, const uint32_t* a, const uint32_t* b) {
    asm volatile(
        "mma.sync.aligned.m16n8k16.row.col.f32.bf16.bf16.f32 "
        "{%0,%1,%2,%3}, {%4,%5,%6,%7}, {%8,%9}, {%0,%1,%2,%3};\n"
        : "+f"(c[0]), "+f"(c[1]), "+f"(c[2]), "+f"(c[3])
        : "r"(a[0]), "r"(a[1]), "r"(a[2]), "r"(a[3]), "r"(b[0]), "r"(b[1]));
}

__device__ __forceinline__ void ldsm_x4(uint32_t addr, uint32_t* r) {
    asm volatile("ldmatrix.sync.aligned.m8n8.x4.shared.b16 {%0,%1,%2,%3}, [%4];"
                 : "=r"(r[0]), "=r"(r[1]), "=r"(r[2]), "=r"(r[3]) : "r"(addr));
}
__device__ __forceinline__ void ldsm_x2(uint32_t addr, uint32_t* r) {
    asm volatile("ldmatrix.sync.aligned.m8n8.x2.shared.b16 {%0,%1}, [%2];"
                 : "=r"(r[0]), "=r"(r[1]) : "r"(addr));
}

__device__ __forceinline__ void cpasync16(void* dst_smem, const void* src) {
    uint32_t d = (uint32_t)__cvta_generic_to_shared(dst_smem);
    asm volatile("cp.async.cg.shared.global [%0], [%1], 16;\n" :: "r"(d), "l"(src) : "memory");
}
__device__ __forceinline__ void cpasync_commit() {
    asm volatile("cp.async.commit_group;\n" ::: "memory");
}
template <int N>
__device__ __forceinline__ void cpasync_wait() {
    asm volatile("cp.async.wait_group %0;\n" :: "n"(N) : "memory");
}

__device__ __forceinline__ unsigned long long umin64(unsigned long long a, unsigned long long b) {
    return a < b ? a : b;
}

// Reference-numerics emulation (validated round 5):
// a = ascending-k fp32 FFMA chain; dist = fl(fl(rn - 2a) + cn)
__device__ __forceinline__ float emul_dist(const float* __restrict__ X, int col, float rn_em) {
    const float* e = g_embT + (size_t)col * DIMD;
    float a = 0.f;
    for (int d = 0; d < DIMD; d++)
        a = fmaf(X[d], e[d], a);
    return __fadd_rn(__fsub_rn(rn_em, 2.0f * a), g_cn[col]);
}

// rn emulation: lane-strided fp32 mul+add, shfl-down tree (full warp required)
__device__ __forceinline__ float emul_rn(const float* __restrict__ X, int lane) {
    float s = 0.f;
    #pragma unroll
    for (int j = 0; j < 8; j++) {
        float v = X[lane + 32 * j];
        s = __fadd_rn(s, __fmul_rn(v, v));
    }
    #pragma unroll
    for (int off = 16; off; off >>= 1)
        s = __fadd_rn(s, __shfl_down_sync(0xffffffffu, s, off));
    return __shfl_sync(0xffffffffu, s, 0);
}

// ---------------- K1: prep codebook (one warp per code) ----------------
__global__ void vq_prep_kernel(const float* __restrict__ embed) {
    const int warp = threadIdx.x >> 5, lane = threadIdx.x & 31;
    const int k = blockIdx.x * 8 + warp;      // grid 128 x 8 warps = 1024
    if (blockIdx.x == 0 && threadIdx.x == 0) {
        g_diff[0] = 0.0; g_diff[1] = 0.0; g_done = 0u;
    }
    double s = 0.0;
    #pragma unroll
    for (int j = 0; j < 8; j++) {
        int d = lane + 32 * j;
        float v = embed[d * KCB + k];
        g_embT[k * DIMD + d] = v;
        g_Eb[k * DIMD + d] = __float2bfloat16(v);
        s = fma((double)v, (double)v, s);
    }
    #pragma unroll
    for (int off = 16; off; off >>= 1)
        s += __shfl_down_sync(0xffffffffu, s, off);
    if (lane == 0) g_cn[k] = (float)s;
}

// ---------------- K2: fused dist + candidates + argmin + ste + diff + finalize
// E double buffer (36864 B) is reused as the dist staging tile (64*132*4 = 33792 B)
// during each nc epilogue, after the mainloop for that nc has fully consumed it.
static constexpr size_t SMEM_BYTES =
    (size_t)BM * XP * 2            // X bf16                     33792
    + 2ull * BN * EP * 2           // E double buffer bf16       36864
    + (BN + BM) * 4                // cn, rn                       768
    + BM * 8                       // minkey                       512
    + (size_t)BM * CAP * 8         // candidate list             12288
    + BM * 4;                      // candidate counts             256
// = 84480 bytes -> 2 CTAs/SM

__global__ __launch_bounds__(THREADS, 2)
void vq_main_kernel(const float* __restrict__ in_hr,
                    const float* __restrict__ in_lr,
                    float* __restrict__ out) {
    extern __shared__ char smem[];
    __nv_bfloat16* sX = (__nv_bfloat16*)smem;
    __nv_bfloat16* sE = sX + BM * XP;               // [2 buf][BN*EP]
    float* stage = (float*)sE;                      // epilogue reuse: [BM][SP]
    float* cn_s = (float*)((char*)sE + 2 * BN * EP * 2);
    float* rn_s = cn_s + BN;
    unsigned long long* minkey = (unsigned long long*)(rn_s + BM);
    unsigned long long* cand   = minkey + BM;       // [BM][CAP]
    int* ccnt = (int*)(cand + BM * CAP);

    const int tid  = threadIdx.x;
    const int bid  = blockIdx.x;
    const int input = bid >> 9;                 // 0: hr, 1: lr   (512 blocks each)
    const int lrb   = (bid & 511) * BM;         // local row base within input
    const float* X = (input == 0 ? in_hr : in_lr) + (size_t)lrb * DIMD;

    // ---- load X -> bf16 smem ----
    const float4* Xv = (const float4*)X;
    for (int i = tid; i < BM * DIMD / 4; i += THREADS) {
        float4 v = Xv[i];
        int row = i >> 6;
        int col = (i & 63) * 4;
        __nv_bfloat16* p = sX + row * XP + col;
        p[0] = __float2bfloat16(v.x);
        p[1] = __float2bfloat16(v.y);
        p[2] = __float2bfloat16(v.z);
        p[3] = __float2bfloat16(v.w);
    }
    if (tid < BM) { minkey[tid] = ~0ull; ccnt[tid] = 0; }

    // ---- row norms in fp64 (for the dist OUTPUT; tolerance loose) ----
    {
        int r  = tid >> 2;                 // 64 rows, 4 threads each
        int d0 = (tid & 3) * 64;
        const float* xp = X + r * DIMD + d0;
        double s = 0.0;
        #pragma unroll 4
        for (int d = 0; d < 64; d++) {
            double x = (double)xp[d];
            s = fma(x, x, s);
        }
        s += __shfl_down_sync(0xffffffffu, s, 2);
        s += __shfl_down_sync(0xffffffffu, s, 1);
        if ((tid & 3) == 0) rn_s[r] = (float)s;
    }
    __syncthreads();

    const int warp = tid >> 5, lane = tid & 31;
    const int wm = warp >> 2, wn = warp & 3;    // warp grid 2 (M) x 4 (N)
    const int g = lane >> 2, tg = lane & 3;
    const int rowA0 = wm * 32 + g;              // + mt*16 (+8)

    // ldmatrix lane->address offsets (in halves)
    int aRowOff[2], bRowOff[4];
    #pragma unroll
    for (int mt = 0; mt < 2; mt++)
        aRowOff[mt] = (wm * 32 + mt * 16 + (lane & 15)) * XP + (lane >> 4) * 8;
    #pragma unroll
    for (int nt = 0; nt < 4; nt++)
        bRowOff[nt] = (wn * 32 + nt * 8 + (lane & 7)) * EP + ((lane >> 3) & 1) * 8;

    const uint32_t sX_sa = (uint32_t)__cvta_generic_to_shared(sX);
    const uint32_t sE_sa = (uint32_t)__cvta_generic_to_shared(sE);

    float acc[2][4][4];

    for (int nc = 0; nc < NCH; nc++) {
        __syncthreads();   // staging read-pass (prev nc) done before E prefetch
        if (tid < BN) cn_s[tid] = g_cn[nc * BN + tid];
        #pragma unroll
        for (int mt = 0; mt < 2; mt++)
            #pragma unroll
            for (int nt = 0; nt < 4; nt++)
                #pragma unroll
                for (int j = 0; j < 4; j++) acc[mt][nt][j] = 0.f;

        // prefetch dchunk 0: 128 rows x 64 bf16 (128B = 8 x 16B per row)
        {
            __nv_bfloat16* dst = sE;
            for (int i = tid; i < 1024; i += THREADS) {
                int row = i >> 3, seg = i & 7;
                size_t go = (size_t)(nc * BN + row) * DIMD + seg * 8;
                cpasync16(dst + row * EP + seg * 8, g_Eb + go);
            }
            cpasync_commit();
        }

        for (int dcx = 0; dcx < DCH; dcx++) {
            int cur = dcx & 1;
            if (dcx < DCH - 1) {
                __nv_bfloat16* dst = sE + (cur ^ 1) * BN * EP;
                int dcn = dcx + 1;
                for (int i = tid; i < 1024; i += THREADS) {
                    int row = i >> 3, seg = i & 7;
                    size_t go = (size_t)(nc * BN + row) * DIMD + dcn * DC + seg * 8;
                    cpasync16(dst + row * EP + seg * 8, g_Eb + go);
                }
                cpasync_commit();
                cpasync_wait<1>();
            } else {
                cpasync_wait<0>();
            }
            __syncthreads();

            const uint32_t Ec_sa = sE_sa + cur * BN * EP * 2;

            #pragma unroll
            for (int ks = 0; ks < 4; ks++) {
                uint32_t a[2][4], b[4][2];
                const int dA = dcx * DC + ks * 16;
                #pragma unroll
                for (int mt = 0; mt < 2; mt++)
                    ldsm_x4(sX_sa + (aRowOff[mt] + dA) * 2, a[mt]);
                #pragma unroll
                for (int nt = 0; nt < 4; nt++)
                    ldsm_x2(Ec_sa + (bRowOff[nt] + ks * 16) * 2, b[nt]);
                #pragma unroll
                for (int mt = 0; mt < 2; mt++)
                    #pragma unroll
                    for (int nt = 0; nt < 4; nt++)
                        mma16816(acc[mt][nt], a[mt], b[nt]);
            }
            __syncthreads();   // last dcx: doubles as the pre-staging barrier
        }

        // ---- epilogue: stage dist in smem, running argmin, candidates ----
        {
            #pragma unroll
            for (int mt = 0; mt < 2; mt++) {
                const int rA = rowA0 + mt * 16;
                const int rB = rA + 8;
                const float rnA = rn_s[rA], rnB = rn_s[rB];
                float vA[8], vB[8];
                unsigned long long kA = ~0ull, kB = ~0ull;
                #pragma unroll
                for (int nt = 0; nt < 4; nt++) {
                    const int c  = wn * 32 + nt * 8 + tg * 2;
                    const int gc = nc * BN + c;
                    const float cn0 = cn_s[c], cn1 = cn_s[c + 1];
                    const float* a = acc[mt][nt];
                    float v00 = fmaf(-2.0f, a[0], rnA) + cn0;
                    float v01 = fmaf(-2.0f, a[1], rnA) + cn1;
                    float v10 = fmaf(-2.0f, a[2], rnB) + cn0;
                    float v11 = fmaf(-2.0f, a[3], rnB) + cn1;
                    vA[nt * 2] = v00; vA[nt * 2 + 1] = v01;
                    vB[nt * 2] = v10; vB[nt * 2 + 1] = v11;
                    *(float2*)(stage + rA * SP + c) = make_float2(v00, v01);
                    *(float2*)(stage + rB * SP + c) = make_float2(v10, v11);
                    unsigned long long k00 = ((unsigned long long)__float_as_uint(v00) << 32) | (unsigned)gc;
                    unsigned long long k01 = ((unsigned long long)__float_as_uint(v01) << 32) | (unsigned)(gc + 1);
                    unsigned long long k10 = ((unsigned long long)__float_as_uint(v10) << 32) | (unsigned)gc;
                    unsigned long long k11 = ((unsigned long long)__float_as_uint(v11) << 32) | (unsigned)(gc + 1);
                    kA = umin64(kA, umin64(k00, k01));
                    kB = umin64(kB, umin64(k10, k11));
                }
                kA = umin64(kA, __shfl_xor_sync(0xffffffffu, kA, 1));
                kA = umin64(kA, __shfl_xor_sync(0xffffffffu, kA, 2));
                kB = umin64(kB, __shfl_xor_sync(0xffffffffu, kB, 1));
                kB = umin64(kB, __shfl_xor_sync(0xffffffffu, kB, 2));

                // reference levels for collection (>= final min -> superset)
                const float refA = __uint_as_float((unsigned)(umin64(minkey[rA], kA) >> 32)) + THR;
                const float refB = __uint_as_float((unsigned)(umin64(minkey[rB], kB) >> 32)) + THR;
                #pragma unroll
                for (int nt = 0; nt < 4; nt++) {
                    const int gc = nc * BN + wn * 32 + nt * 8 + tg * 2;
                    #pragma unroll
                    for (int q = 0; q < 2; q++) {
                        if (vA[nt * 2 + q] <= refA) {
                            int p = atomicAdd(&ccnt[rA], 1);
                            if (p < CAP)
                                cand[rA * CAP + p] =
                                    ((unsigned long long)__float_as_uint(vA[nt * 2 + q]) << 32) | (unsigned)(gc + q);
                        }
                        if (vB[nt * 2 + q] <= refB) {
                            int p = atomicAdd(&ccnt[rB], 1);
                            if (p < CAP)
                                cand[rB * CAP + p] =
                                    ((unsigned long long)__float_as_uint(vB[nt * 2 + q]) << 32) | (unsigned)(gc + q);
                        }
                    }
                }
                if (tg == 0) {
                    atomicMin(&minkey[rA], kA);
                    atomicMin(&minkey[rB], kB);
                }
            }
        }
        __syncthreads();

        // ---- coalesced store pass: 512B per STG.128 instruction, streaming ----
        {
            const size_t dbase = O_DIST + (size_t)input * DIST_SZ
                                 + (size_t)lrb * KCB + (size_t)nc * BN;
            #pragma unroll
            for (int rr = 0; rr < 8; rr++) {
                const int r = warp * 8 + rr;
                float4 v = *(const float4*)(stage + r * SP + lane * 4);
                float* p = out + dbase + (size_t)r * KCB + lane * 4;
                __stcs((float4*)p, v);
                __stcs((float4*)(p + 2ull * DIST_SZ), v);
            }
        }
    }
    __syncthreads();

    // ---- final epilogue: tie resolution, indices, gather, ste, diff ----
    {
        double dsum = 0.0;
        const size_t steA = (size_t)input * STE_SZ;
        const size_t steB = steA + 2ull * STE_SZ;
        const size_t indA = O_IND + (size_t)input * NROW;
        const size_t indB = indA + 2ull * NROW;
        for (int rr = 0; rr < 8; rr++) {
            const int r = warp * 8 + rr;
            const unsigned long long fkey = minkey[r];
            const float fminv = __uint_as_float((unsigned)(fkey >> 32));
            const int cnt = ccnt[r];
            const float* Xr = X + (size_t)r * DIMD;

            unsigned win;
            if (cnt <= CAP) {
                unsigned long long ck = (lane < cnt) ? cand[r * CAP + lane] : ~0ull;
                float cv = __uint_as_float((unsigned)(ck >> 32));
                bool qual = (lane < cnt) && (cv <= fminv + THR);
                unsigned bal = __ballot_sync(0xffffffffu, qual);
                if (__popc(bal) == 1) {
                    win = (unsigned)(fkey & 0xffffffffull);
                } else {
                    const float rn_em = emul_rn(Xr, lane);
                    unsigned long long key = ~0ull;
                    if (qual) {
                        const int cc = (int)(ck & 0xffffffffull);
                        float dd = emul_dist(Xr, cc, rn_em);
                        key = ((unsigned long long)__float_as_uint(dd) << 32) | (unsigned)cc;
                    }
                    #pragma unroll
                    for (int off = 16; off; off >>= 1)
                        key = umin64(key, __shfl_xor_sync(0xffffffffu, key, off));
                    win = (unsigned)(key & 0xffffffffull);
                }
            } else {
                // overflow fallback: rescan the written dist row (L2-hot)
                const float rn_em = emul_rn(Xr, lane);
                const float* drow = out + O_DIST + (size_t)input * DIST_SZ
                                    + (size_t)(lrb + r) * KCB;
                unsigned long long key = ~0ull;
                for (int j = 0; j < 32; j++) {
                    int c = lane + 32 * j;
                    float v = drow[c];
                    if (v <= fminv + THR) {
                        float dd = emul_dist(Xr, c, rn_em);
                        key = umin64(key,
                            ((unsigned long long)__float_as_uint(dd) << 32) | (unsigned)c);
                    }
                }
                #pragma unroll
                for (int off = 16; off; off >>= 1)
                    key = umin64(key, __shfl_xor_sync(0xffffffffu, key, off));
                win = (unsigned)(key & 0xffffffffull);
            }

            const size_t grow = (size_t)(lrb + r);
            if (lane == 0) {
                float fi = (float)win;
                out[indA + grow] = fi;
                out[indB + grow] = fi;
            }
            const float4* qp = (const float4*)(g_embT + (size_t)win * DIMD) + lane * 2;
            const float4 q0 = qp[0], q1 = qp[1];
            const float4* xg = (const float4*)Xr + lane * 2;
            const float4 x0 = xg[0], x1 = xg[1];
            float xr[8] = {x0.x, x0.y, x0.z, x0.w, x1.x, x1.y, x1.z, x1.w};
            float qv[8] = {q0.x, q0.y, q0.z, q0.w, q1.x, q1.y, q1.z, q1.w};
            float sv[8];
            float fs = 0.f;
            #pragma unroll
            for (int j = 0; j < 8; j++) {
                float dv = __fsub_rn(qv[j], xr[j]);
                sv[j] = __fadd_rn(xr[j], dv);     // exact STE forward as in reference
                fs = fmaf(dv, dv, fs);
            }
            dsum += (double)fs;
            const size_t o = grow * DIMD + lane * 8;
            __stcs((float4*)(out + steA + o),     make_float4(sv[0], sv[1], sv[2], sv[3]));
            __stcs((float4*)(out + steA + o + 4), make_float4(sv[4], sv[5], sv[6], sv[7]));
            __stcs((float4*)(out + steB + o),     make_float4(sv[0], sv[1], sv[2], sv[3]));
            __stcs((float4*)(out + steB + o + 4), make_float4(sv[4], sv[5], sv[6], sv[7]));
        }
        #pragma unroll
        for (int off = 16; off > 0; off >>= 1)
            dsum += __shfl_down_sync(0xffffffffu, dsum, off);
        if (lane == 0) atomicAdd(&g_diff[input], dsum);
    }

    // ---- in-kernel finalize: last CTA to finish writes the diff outputs ----
    __syncthreads();                 // all warps' g_diff atomics issued
    if (tid == 0) {
        __threadfence();             // make this CTA's g_diff update visible
        unsigned prev = atomicAdd(&g_done, 1u);
        if (prev == gridDim.x - 1u) {
            __threadfence();         // acquire all other CTAs' g_diff updates
            float dh = (float)(g_diff[0] / (double)STE_SZ);
            float dl = (float)(g_diff[1] / (double)STE_SZ);
            out[O_DIFF + 0] = dh;
            out[O_DIFF + 1] = dl;
            out[O_DIFF + 2] = dh;
            out[O_DIFF + 3] = dl;
        }
    }
}

// ---------------- launch ----------------
extern "C" void kernel_launch(void* const* d_in, const int* in_sizes, int n_in,
                              void* d_out, int out_size) {
    const float* in_hr = (const float*)d_in[0];
    const float* in_lr = (const float*)d_in[1];
    const float* embed = (const float*)d_in[2];
    float* out = (float*)d_out;
    (void)in_sizes; (void)n_in; (void)out_size;

    cudaFuncSetAttribute(vq_main_kernel,
                         cudaFuncAttributeMaxDynamicSharedMemorySize,
                         (int)SMEM_BYTES);

    vq_prep_kernel<<<128, 256>>>(embed);
    vq_main_kernel<<<ROWS / BM, THREADS, SMEM_BYTES>>>(in_hr, in_lr, out);
}

// round 13
// speedup vs baseline: 2.1884x; 1.0039x over previous
#include <cuda_runtime.h>
#include <cuda_bf16.h>
#include <cstdint>

// ---------------- problem constants ----------------
static constexpr int DIMD   = 256;     // embedding dim (GEMM K)
static constexpr int KCB    = 1024;    // codebook size (GEMM N)
static constexpr int NROW   = 32768;   // rows per input
static constexpr int ROWS   = 65536;   // both inputs
static constexpr int BM     = 64;      // rows per block
static constexpr int BN     = 128;     // cols per n-chunk
static constexpr int NCH    = KCB / BN;   // 8
static constexpr int THREADS = 256;
static constexpr int CAP    = 16;      // candidate list capacity per row
static constexpr float THR  = 0.01f;   // candidate threshold (>>12 sigma of bf16 noise)

static constexpr int XP  = DIMD + 8;   // 264 bf16, X smem pitch
static constexpr int EPL = 136;        // bf16, E smem pitch for 128-col chunks (68 words % 32 == 4)
static constexpr int SP  = BN + 4;     // 132 fp32, dist staging pitch

// ---------------- output layout (fp32 elements) ----------------
static constexpr size_t STE_SZ  = 8388608;            // 8*64*64*256
static constexpr size_t O_DIFF  = 4ull * STE_SZ;      // 33554432
static constexpr size_t O_IND   = O_DIFF + 4;         // 33554436
static constexpr size_t O_DIST  = O_IND + 4ull * NROW;// 33685508
static constexpr size_t DIST_SZ = (size_t)NROW * KCB; // 33554432

// ---------------- device scratch (no allocations allowed) ----------------
__device__ __align__(16) __nv_bfloat16 g_Eb[KCB * DIMD];    // [k][d] bf16
__device__ __align__(16) float         g_embT[KCB * DIMD];  // [k][d] fp32
__device__ float  g_cn[KCB];
__device__ double g_diff[2];
__device__ unsigned g_done;            // completion counter for in-kernel finalize

// ---------------- helpers ----------------
__device__ __forceinline__ void mma16816(float* c, const uint32_t* a, const uint32_t* b) {
    asm volatile(
        "mma.sync.aligned.m16n8k16.row.col.f32.bf16.bf16.f32 "
        "{%0,%1,%2,%3}, {%4,%5,%6,%7}, {%8,%9}, {%0,%1,%2,%3};\n"
        : "+f"(c[0]), "+f"(c[1]), "+f"(c[2]), "+f"(c[3])
        : "r"(a[0]), "r"(a[1]), "r"(a[2]), "r"(a[3]), "r"(b[0]), "r"(b[1]));
}

__device__ __forceinline__ void ldsm_x4(uint32_t addr, uint32_t* r) {
    asm volatile("ldmatrix.sync.aligned.m8n8.x4.shared.b16 {%0,%1,%2,%3}, [%4];"
                 : "=r"(r[0]), "=r"(r[1]), "=r"(r[2]), "=r"(r[3]) : "r"(addr));
}
__device__ __forceinline__ void ldsm_x2(uint32_t addr, uint32_t* r) {
    asm volatile("ldmatrix.sync.aligned.m8n8.x2.shared.b16 {%0,%1}, [%2];"
                 : "=r"(r[0]), "=r"(r[1]) : "r"(addr));
}

__device__ __forceinline__ void cpasync16(void* dst_smem, const void* src) {
    uint32_t d = (uint32_t)__cvta_generic_to_shared(dst_smem);
    asm volatile("cp.async.cg.shared.global [%0], [%1], 16;\n" :: "r"(d), "l"(src) : "memory");
}
__device__ __forceinline__ void cpasync_commit() {
    asm volatile("cp.async.commit_group;\n" ::: "memory");
}
template <int N>
__device__ __forceinline__ void cpasync_wait() {
    asm volatile("cp.async.wait_group %0;\n" :: "n"(N) : "memory");
}

__device__ __forceinline__ unsigned long long umin64(unsigned long long a, unsigned long long b) {
    return a < b ? a : b;
}

// Reference-numerics emulation (validated round 5):
// a = ascending-k fp32 FFMA chain; dist = fl(fl(rn - 2a) + cn)
__device__ __forceinline__ float emul_dist(const float* __restrict__ X, int col, float rn_em) {
    const float* e = g_embT + (size_t)col * DIMD;
    float a = 0.f;
    for (int d = 0; d < DIMD; d++)
        a = fmaf(X[d], e[d], a);
    return __fadd_rn(__fsub_rn(rn_em, 2.0f * a), g_cn[col]);
}

// rn emulation: lane-strided fp32 mul+add, shfl-down tree (full warp required)
__device__ __forceinline__ float emul_rn(const float* __restrict__ X, int lane) {
    float s = 0.f;
    #pragma unroll
    for (int j = 0; j < 8; j++) {
        float v = X[lane + 32 * j];
        s = __fadd_rn(s, __fmul_rn(v, v));
    }
    #pragma unroll
    for (int off = 16; off; off >>= 1)
        s = __fadd_rn(s, __shfl_down_sync(0xffffffffu, s, off));
    return __shfl_sync(0xffffffffu, s, 0);
}

// ---------------- K1: prep codebook (one warp per code) ----------------
__global__ void vq_prep_kernel(const float* __restrict__ embed) {
    const int warp = threadIdx.x >> 5, lane = threadIdx.x & 31;
    const int k = blockIdx.x * 8 + warp;      // grid 128 x 8 warps = 1024
    if (blockIdx.x == 0 && threadIdx.x == 0) {
        g_diff[0] = 0.0; g_diff[1] = 0.0; g_done = 0u;
    }
    double s = 0.0;
    #pragma unroll
    for (int j = 0; j < 8; j++) {
        int d = lane + 32 * j;
        float v = embed[d * KCB + k];
        g_embT[k * DIMD + d] = v;
        g_Eb[k * DIMD + d] = __float2bfloat16(v);
        s = fma((double)v, (double)v, s);
    }
    #pragma unroll
    for (int off = 16; off; off >>= 1)
        s += __shfl_down_sync(0xffffffffu, s, off);
    if (lane == 0) g_cn[k] = (float)s;
}

// ---------------- K2: fused dist + candidates + argmin + ste + diff + finalize
// E double buffer: 2 x [128 rows x 128 cols] bf16 chunks (EPL pitch).
// Buffer 1's region doubles as the fp32 dist staging tile after the mainloop.
static constexpr size_t SMEM_BYTES =
    (size_t)BM * XP * 2            // X bf16                     33792
    + 2ull * BN * EPL * 2          // E double buffer bf16       69632
    + (BN + BM) * 4                // cn, rn                       768
    + BM * 8                       // minkey                       512
    + (size_t)BM * CAP * 8         // candidate list              8192
    + BM * 4;                      // candidate counts             256
// = 113152 bytes -> 2 CTAs/SM

__global__ __launch_bounds__(THREADS, 2)
void vq_main_kernel(const float* __restrict__ in_hr,
                    const float* __restrict__ in_lr,
                    float* __restrict__ out) {
    extern __shared__ char smem[];
    __nv_bfloat16* sX = (__nv_bfloat16*)smem;
    __nv_bfloat16* sE = sX + BM * XP;               // [2 buf][BN*EPL]
    float* stage = (float*)(sE + BN * EPL);         // buf1 region reuse: [BM][SP]
    float* cn_s = (float*)((char*)sE + 2 * BN * EPL * 2);
    float* rn_s = cn_s + BN;
    unsigned long long* minkey = (unsigned long long*)(rn_s + BM);
    unsigned long long* cand   = minkey + BM;       // [BM][CAP]
    int* ccnt = (int*)(cand + BM * CAP);

    const int tid  = threadIdx.x;
    const int bid  = blockIdx.x;
    const int input = bid >> 9;                 // 0: hr, 1: lr   (512 blocks each)
    const int lrb   = (bid & 511) * BM;         // local row base within input
    const float* X = (input == 0 ? in_hr : in_lr) + (size_t)lrb * DIMD;

    // ---- prefetch E chunk (nc=0, dcx=0) -> buf0 ----
    for (int i = tid; i < 2048; i += THREADS) {
        int row = i >> 4, seg = i & 15;
        size_t go = (size_t)row * DIMD + seg * 8;
        cpasync16(sE + row * EPL + seg * 8, g_Eb + go);
    }
    cpasync_commit();

    // ---- load X -> bf16 smem ----
    const float4* Xv = (const float4*)X;
    for (int i = tid; i < BM * DIMD / 4; i += THREADS) {
        float4 v = Xv[i];
        int row = i >> 6;
        int col = (i & 63) * 4;
        __nv_bfloat16* p = sX + row * XP + col;
        p[0] = __float2bfloat16(v.x);
        p[1] = __float2bfloat16(v.y);
        p[2] = __float2bfloat16(v.z);
        p[3] = __float2bfloat16(v.w);
    }
    if (tid < BM) { minkey[tid] = ~0ull; ccnt[tid] = 0; }

    // ---- row norms in fp64 (for the dist OUTPUT; tolerance loose) ----
    {
        int r  = tid >> 2;                 // 64 rows, 4 threads each
        int d0 = (tid & 3) * 64;
        const float* xp = X + r * DIMD + d0;
        double s = 0.0;
        #pragma unroll 4
        for (int d = 0; d < 64; d++) {
            double x = (double)xp[d];
            s = fma(x, x, s);
        }
        s += __shfl_down_sync(0xffffffffu, s, 2);
        s += __shfl_down_sync(0xffffffffu, s, 1);
        if ((tid & 3) == 0) rn_s[r] = (float)s;
    }
    __syncthreads();

    const int warp = tid >> 5, lane = tid & 31;
    const int wm = warp >> 2, wn = warp & 3;    // warp grid 2 (M) x 4 (N)
    const int g = lane >> 2, tg = lane & 3;
    const int rowA0 = wm * 32 + g;              // + mt*16 (+8)

    // ldmatrix lane->address offsets (in halves)
    int aRowOff[2], bRowOff[4];
    #pragma unroll
    for (int mt = 0; mt < 2; mt++)
        aRowOff[mt] = (wm * 32 + mt * 16 + (lane & 15)) * XP + (lane >> 4) * 8;
    #pragma unroll
    for (int nt = 0; nt < 4; nt++)
        bRowOff[nt] = (wn * 32 + nt * 8 + (lane & 7)) * EPL + ((lane >> 3) & 1) * 8;

    const uint32_t sX_sa = (uint32_t)__cvta_generic_to_shared(sX);
    const uint32_t sE_sa = (uint32_t)__cvta_generic_to_shared(sE);

    float acc[2][4][4];

    for (int nc = 0; nc < NCH; nc++) {
        // cn for this n-chunk (prev readers separated by two barriers)
        if (tid < BN) cn_s[tid] = g_cn[nc * BN + tid];
        #pragma unroll
        for (int mt = 0; mt < 2; mt++)
            #pragma unroll
            for (int nt = 0; nt < 4; nt++)
                #pragma unroll
                for (int j = 0; j < 4; j++) acc[mt][nt][j] = 0.f;

        // prefetch chunk dcx=1 -> buf1 (buf1 drained last iteration, barrier passed)
        {
            __nv_bfloat16* dst = sE + BN * EPL;
            for (int i = tid; i < 2048; i += THREADS) {
                int row = i >> 4, seg = i & 15;
                size_t go = (size_t)(nc * BN + row) * DIMD + 128 + seg * 8;
                cpasync16(dst + row * EPL + seg * 8, g_Eb + go);
            }
            cpasync_commit();
        }
        cpasync_wait<1>();      // buf0 (issued last iteration / pre-loop) done
        __syncthreads();

        // ---- mainloop chunk 0 (buf0): 8 ks straight-line ----
        #pragma unroll
        for (int ks = 0; ks < 8; ks++) {
            uint32_t a[2][4], b[4][2];
            const int dA = ks * 16;
            #pragma unroll
            for (int mt = 0; mt < 2; mt++)
                ldsm_x4(sX_sa + (aRowOff[mt] + dA) * 2, a[mt]);
            #pragma unroll
            for (int nt = 0; nt < 4; nt++)
                ldsm_x2(sE_sa + (bRowOff[nt] + ks * 16) * 2, b[nt]);
            #pragma unroll
            for (int mt = 0; mt < 2; mt++)
                #pragma unroll
                for (int nt = 0; nt < 4; nt++)
                    mma16816(acc[mt][nt], a[mt], b[nt]);
        }
        cpasync_wait<0>();      // buf1 done (load overlapped with chunk-0 math)
        __syncthreads();

        // ---- mainloop chunk 1 (buf1): 8 ks straight-line ----
        {
            const uint32_t Ec_sa = sE_sa + BN * EPL * 2;
            #pragma unroll
            for (int ks = 0; ks < 8; ks++) {
                uint32_t a[2][4], b[4][2];
                const int dA = 128 + ks * 16;
                #pragma unroll
                for (int mt = 0; mt < 2; mt++)
                    ldsm_x4(sX_sa + (aRowOff[mt] + dA) * 2, a[mt]);
                #pragma unroll
                for (int nt = 0; nt < 4; nt++)
                    ldsm_x2(Ec_sa + (bRowOff[nt] + ks * 16) * 2, b[nt]);
                #pragma unroll
                for (int mt = 0; mt < 2; mt++)
                    #pragma unroll
                    for (int nt = 0; nt < 4; nt++)
                        mma16816(acc[mt][nt], a[mt], b[nt]);
            }
        }
        __syncthreads();        // all buf1 reads done before staging overwrites it

        // ---- epilogue: stage dist in smem (buf1 region), argmin, candidates --
        {
            #pragma unroll
            for (int mt = 0; mt < 2; mt++) {
                const int rA = rowA0 + mt * 16;
                const int rB = rA + 8;
                const float rnA = rn_s[rA], rnB = rn_s[rB];
                float vA[8], vB[8];
                unsigned long long kA = ~0ull, kB = ~0ull;
                #pragma unroll
                for (int nt = 0; nt < 4; nt++) {
                    const int c  = wn * 32 + nt * 8 + tg * 2;
                    const int gc = nc * BN + c;
                    const float cn0 = cn_s[c], cn1 = cn_s[c + 1];
                    const float* a = acc[mt][nt];
                    float v00 = fmaf(-2.0f, a[0], rnA) + cn0;
                    float v01 = fmaf(-2.0f, a[1], rnA) + cn1;
                    float v10 = fmaf(-2.0f, a[2], rnB) + cn0;
                    float v11 = fmaf(-2.0f, a[3], rnB) + cn1;
                    vA[nt * 2] = v00; vA[nt * 2 + 1] = v01;
                    vB[nt * 2] = v10; vB[nt * 2 + 1] = v11;
                    *(float2*)(stage + rA * SP + c) = make_float2(v00, v01);
                    *(float2*)(stage + rB * SP + c) = make_float2(v10, v11);
                    unsigned long long k00 = ((unsigned long long)__float_as_uint(v00) << 32) | (unsigned)gc;
                    unsigned long long k01 = ((unsigned long long)__float_as_uint(v01) << 32) | (unsigned)(gc + 1);
                    unsigned long long k10 = ((unsigned long long)__float_as_uint(v10) << 32) | (unsigned)gc;
                    unsigned long long k11 = ((unsigned long long)__float_as_uint(v11) << 32) | (unsigned)(gc + 1);
                    kA = umin64(kA, umin64(k00, k01));
                    kB = umin64(kB, umin64(k10, k11));
                }
                kA = umin64(kA, __shfl_xor_sync(0xffffffffu, kA, 1));
                kA = umin64(kA, __shfl_xor_sync(0xffffffffu, kA, 2));
                kB = umin64(kB, __shfl_xor_sync(0xffffffffu, kB, 1));
                kB = umin64(kB, __shfl_xor_sync(0xffffffffu, kB, 2));

                // reference levels for collection (>= final min -> superset)
                const float refA = __uint_as_float((unsigned)(umin64(minkey[rA], kA) >> 32)) + THR;
                const float refB = __uint_as_float((unsigned)(umin64(minkey[rB], kB) >> 32)) + THR;
                #pragma unroll
                for (int nt = 0; nt < 4; nt++) {
                    const int gc = nc * BN + wn * 32 + nt * 8 + tg * 2;
                    #pragma unroll
                    for (int q = 0; q < 2; q++) {
                        if (vA[nt * 2 + q] <= refA) {
                            int p = atomicAdd(&ccnt[rA], 1);
                            if (p < CAP)
                                cand[rA * CAP + p] =
                                    ((unsigned long long)__float_as_uint(vA[nt * 2 + q]) << 32) | (unsigned)(gc + q);
                        }
                        if (vB[nt * 2 + q] <= refB) {
                            int p = atomicAdd(&ccnt[rB], 1);
                            if (p < CAP)
                                cand[rB * CAP + p] =
                                    ((unsigned long long)__float_as_uint(vB[nt * 2 + q]) << 32) | (unsigned)(gc + q);
                        }
                    }
                }
                if (tg == 0) {
                    atomicMin(&minkey[rA], kA);
                    atomicMin(&minkey[rB], kB);
                }
            }
        }
        __syncthreads();

        // ---- drain stage -> global (512B STG.128, streaming) + next prefetch
        {
            const size_t dbase = O_DIST + (size_t)input * DIST_SZ
                                 + (size_t)lrb * KCB + (size_t)nc * BN;
            #pragma unroll
            for (int rr = 0; rr < 8; rr++) {
                const int r = warp * 8 + rr;
                float4 v = *(const float4*)(stage + r * SP + lane * 4);
                float* p = out + dbase + (size_t)r * KCB + lane * 4;
                __stcs((float4*)p, v);
                __stcs((float4*)(p + 2ull * DIST_SZ), v);
            }
        }
        if (nc < NCH - 1) {
            // prefetch next nc chunk 0 -> buf0 (buf0 reads finished pre-epilogue)
            for (int i = tid; i < 2048; i += THREADS) {
                int row = i >> 4, seg = i & 15;
                size_t go = (size_t)((nc + 1) * BN + row) * DIMD + seg * 8;
                cpasync16(sE + row * EPL + seg * 8, g_Eb + go);
            }
            cpasync_commit();
        }
        __syncthreads();        // drains done before buf1 is prefetched next iter
    }

    // ---- final epilogue: tie resolution, indices, gather, ste, diff ----
    {
        double dsum = 0.0;
        const size_t steA = (size_t)input * STE_SZ;
        const size_t steB = steA + 2ull * STE_SZ;
        const size_t indA = O_IND + (size_t)input * NROW;
        const size_t indB = indA + 2ull * NROW;
        for (int rr = 0; rr < 8; rr++) {
            const int r = warp * 8 + rr;
            const unsigned long long fkey = minkey[r];
            const float fminv = __uint_as_float((unsigned)(fkey >> 32));
            const int cnt = ccnt[r];
            const float* Xr = X + (size_t)r * DIMD;

            unsigned win;
            if (cnt <= CAP) {
                unsigned long long ck = (lane < cnt) ? cand[r * CAP + lane] : ~0ull;
                float cv = __uint_as_float((unsigned)(ck >> 32));
                bool qual = (lane < cnt) && (cv <= fminv + THR);
                unsigned bal = __ballot_sync(0xffffffffu, qual);
                if (__popc(bal) == 1) {
                    win = (unsigned)(fkey & 0xffffffffull);
                } else {
                    const float rn_em = emul_rn(Xr, lane);
                    unsigned long long key = ~0ull;
                    if (qual) {
                        const int cc = (int)(ck & 0xffffffffull);
                        float dd = emul_dist(Xr, cc, rn_em);
                        key = ((unsigned long long)__float_as_uint(dd) << 32) | (unsigned)cc;
                    }
                    #pragma unroll
                    for (int off = 16; off; off >>= 1)
                        key = umin64(key, __shfl_xor_sync(0xffffffffu, key, off));
                    win = (unsigned)(key & 0xffffffffull);
                }
            } else {
                // overflow fallback: rescan the written dist row (L2-hot)
                const float rn_em = emul_rn(Xr, lane);
                const float* drow = out + O_DIST + (size_t)input * DIST_SZ
                                    + (size_t)(lrb + r) * KCB;
                unsigned long long key = ~0ull;
                for (int j = 0; j < 32; j++) {
                    int c = lane + 32 * j;
                    float v = drow[c];
                    if (v <= fminv + THR) {
                        float dd = emul_dist(Xr, c, rn_em);
                        key = umin64(key,
                            ((unsigned long long)__float_as_uint(dd) << 32) | (unsigned)c);
                    }
                }
                #pragma unroll
                for (int off = 16; off; off >>= 1)
                    key = umin64(key, __shfl_xor_sync(0xffffffffu, key, off));
                win = (unsigned)(key & 0xffffffffull);
            }

            const size_t grow = (size_t)(lrb + r);
            if (lane == 0) {
                float fi = (float)win;
                out[indA + grow] = fi;
                out[indB + grow] = fi;
            }
            const float4* qp = (const float4*)(g_embT + (size_t)win * DIMD) + lane * 2;
            const float4 q0 = qp[0], q1 = qp[1];
            const float4* xg = (const float4*)Xr + lane * 2;
            const float4 x0 = xg[0], x1 = xg[1];
            float xr[8] = {x0.x, x0.y, x0.z, x0.w, x1.x, x1.y, x1.z, x1.w};
            float qv[8] = {q0.x, q0.y, q0.z, q0.w, q1.x, q1.y, q1.z, q1.w};
            float sv[8];
            float fs = 0.f;
            #pragma unroll
            for (int j = 0; j < 8; j++) {
                float dv = __fsub_rn(qv[j], xr[j]);
                sv[j] = __fadd_rn(xr[j], dv);     // exact STE forward as in reference
                fs = fmaf(dv, dv, fs);
            }
            dsum += (double)fs;
            const size_t o = grow * DIMD + lane * 8;
            __stcs((float4*)(out + steA + o),     make_float4(sv[0], sv[1], sv[2], sv[3]));
            __stcs((float4*)(out + steA + o + 4), make_float4(sv[4], sv[5], sv[6], sv[7]));
            __stcs((float4*)(out + steB + o),     make_float4(sv[0], sv[1], sv[2], sv[3]));
            __stcs((float4*)(out + steB + o + 4), make_float4(sv[4], sv[5], sv[6], sv[7]));
        }
        #pragma unroll
        for (int off = 16; off > 0; off >>= 1)
            dsum += __shfl_down_sync(0xffffffffu, dsum, off);
        if (lane == 0) atomicAdd(&g_diff[input], dsum);
    }

    // ---- in-kernel finalize: last CTA to finish writes the diff outputs ----
    __syncthreads();                 // all warps' g_diff atomics issued
    if (tid == 0) {
        __threadfence();             // make this CTA's g_diff update visible
        unsigned prev = atomicAdd(&g_done, 1u);
        if (prev == gridDim.x - 1u) {
            __threadfence();         // acquire all other CTAs' g_diff updates
            float dh = (float)(g_diff[0] / (double)STE_SZ);
            float dl = (float)(g_diff[1] / (double)STE_SZ);
            out[O_DIFF + 0] = dh;
            out[O_DIFF + 1] = dl;
            out[O_DIFF + 2] = dh;
            out[O_DIFF + 3] = dl;
        }
    }
}

// ---------------- launch ----------------
extern "C" void kernel_launch(void* const* d_in, const int* in_sizes, int n_in,
                              void* d_out, int out_size) {
    const float* in_hr = (const float*)d_in[0];
    const float* in_lr = (const float*)d_in[1];
    const float* embed = (const float*)d_in[2];
    float* out = (float*)d_out;
    (void)in_sizes; (void)n_in; (void)out_size;

    cudaFuncSetAttribute(vq_main_kernel,
                         cudaFuncAttributeMaxDynamicSharedMemorySize,
                         (int)SMEM_BYTES);

    vq_prep_kernel<<<128, 256>>>(embed);
    vq_main_kernel<<<ROWS / BM, THREADS, SMEM_BYTES>>>(in_hr, in_lr, out);
}